// round 14
// baseline (speedup 1.0000x reference)
#include <cuda_runtime.h>
#include <cuda_fp16.h>
#include <math.h>
#include <float.h>
#include <stdint.h>
#include <string.h>

// FILIP loss. B=64, T=64, I=196, D=512.
// sim = text[4096,512] @ vision[12544,512]^T with fused row/col max epilogue.
// fp16 HMMA GEMM (champion config: 128x128 CTA, 8 warps 64x32, 3-stage
// cp.async.bulk pipeline, 2 CTAs/SM). Epilogue prep hoisted; per-warp elected
// empty-barrier arrives (count 8 instead of 256).

#define D_K   512
#define M_TOT 4096
#define N_TOT 12544
#define B_SZ  64
#define I_TOK 196

#define BM 128
#define BN 128
#define BK 64
#define NCHUNK (D_K / BK)            // 8
#define NSTAGE 3
#define TILE_BYTES 16384
#define STAGE_BYTES (2 * TILE_BYTES)
#define DSMEM_BYTES (NSTAGE * STAGE_BYTES)   // 98304 -> 2 CTAs/SM

#define NT_M (M_TOT / BM)            // 32
#define NT_N (N_TOT / BN)            // 98
#define PANEL_W 4

#define ENC_NEG 0x00800000u
#define SWZ128(o) ((o) ^ (((o) >> 3) & 0x70))

__device__ __forceinline__ uint32_t smem_u32(const void* p) {
    uint32_t a;
    asm("{ .reg .u64 t; cvta.to.shared.u64 t, %1; cvt.u32.u64 %0, t; }" : "=r"(a) : "l"(p));
    return a;
}
__device__ __forceinline__ uint32_t h2_u32(half2 h) {
    uint32_t u; memcpy(&u, &h, 4); return u;
}
__device__ __forceinline__ unsigned enc_f(float f) {
    unsigned u = __float_as_uint(f);
    return (u & 0x80000000u) ? ~u : (u | 0x80000000u);
}
__device__ __forceinline__ float dec_f(unsigned u) {
    return __uint_as_float((u & 0x80000000u) ? (u & 0x7FFFFFFFu) : ~u);
}

#define MBAR_INIT(mb, c) asm volatile("mbarrier.init.shared.b64 [%0], %1;" :: "r"(mb), "r"(c) : "memory")
#define MBAR_ARRIVE(mb)  asm volatile("mbarrier.arrive.shared.b64 _, [%0];" :: "r"(mb) : "memory")
#define MBAR_EXPECT_TX(mb, n) asm volatile("mbarrier.arrive.expect_tx.shared.b64 _, [%0], %1;" :: "r"(mb), "r"(n) : "memory")
#define FENCE_ASYNC() asm volatile("fence.proxy.async.shared::cta;" ::: "memory")

#define MBAR_WAIT(mb, par) do { \
    uint32_t _m = (mb), _p = (par), _d; \
    asm volatile("{ .reg .pred p; mbarrier.try_wait.parity.acquire.cta.shared::cta.b64 p, [%1], %2; selp.b32 %0,1,0,p; }" \
        : "=r"(_d) : "r"(_m), "r"(_p) : "memory"); \
    if (!_d) { \
        asm volatile("{ .reg .pred P1; WL_%=: mbarrier.try_wait.parity.acquire.cta.shared::cta.b64 P1, [%0], %1, 0x989680; @P1 bra.uni WD_%=; bra.uni WL_%=; WD_%=: }" \
            :: "r"(_m), "r"(_p) : "memory"); \
    } } while (0)

__device__ __forceinline__ void bulk_g2s(uint32_t dst, const void* src, uint32_t mb) {
    asm volatile("cp.async.bulk.shared::cluster.global.mbarrier::complete_tx::bytes [%0], [%1], %2, [%3];"
        :: "r"(dst), "l"(__cvta_generic_to_global(src)), "r"((uint32_t)TILE_BYTES), "r"(mb) : "memory");
}
__device__ __forceinline__ void ldmx4(uint32_t* r, uint32_t addr) {
    asm volatile("ldmatrix.sync.aligned.m8n8.x4.shared.b16 {%0,%1,%2,%3}, [%4];"
        : "=r"(r[0]), "=r"(r[1]), "=r"(r[2]), "=r"(r[3]) : "r"(addr));
}
__device__ __forceinline__ void mma16816(float* c, const uint32_t* a, uint32_t b0, uint32_t b1) {
    asm volatile("mma.sync.aligned.m16n8k16.row.col.f32.f16.f16.f32 "
        "{%0,%1,%2,%3}, {%4,%5,%6,%7}, {%8,%9}, {%0,%1,%2,%3};"
        : "+f"(c[0]), "+f"(c[1]), "+f"(c[2]), "+f"(c[3])
        : "r"(a[0]), "r"(a[1]), "r"(a[2]), "r"(a[3]), "r"(b0), "r"(b1));
}

// ---------------- scratch ----------------
__device__ __half  Aq[(size_t)M_TOT * D_K];   // tiled+SW128: tile=(rowblk*8+ch)
__device__ __half  Bq[(size_t)N_TOT * D_K];
__device__ unsigned g_rowmax[M_TOT * B_SZ];
__device__ float    g_colmax[B_SZ * N_TOT];
__device__ float    g_t2i_den[B_SZ], g_i2t_den[B_SZ];
__device__ float    g_d1[B_SZ], g_d2[B_SZ];
__device__ int      g_ctr;

// convert (fp32 -> fp16, tiled + SW128 swizzled, 8 elems/thread) + init, fused
__global__ void convert_kernel(const float* __restrict__ text,
                               const float* __restrict__ vision) {
    const int TG = M_TOT * D_K / 8;
    const int VG = N_TOT * D_K / 8;
    int idx = blockIdx.x * blockDim.x + threadIdx.x;
    if (idx < TG + VG) {
        const bool isA = idx < TG;
        const int p = isA ? idx : idx - TG;
        const int row = p >> 6;
        const int k = (p & 63) << 3;
        const float* src = (isA ? text : vision) + (size_t)row * D_K + k;
        float4 v0 = *(const float4*)(src);
        float4 v1 = *(const float4*)(src + 4);
        uint4 h;
        h.x = h2_u32(__floats2half2_rn(v0.x, v0.y));
        h.y = h2_u32(__floats2half2_rn(v0.z, v0.w));
        h.z = h2_u32(__floats2half2_rn(v1.x, v1.y));
        h.w = h2_u32(__floats2half2_rn(v1.z, v1.w));
        const int tile = (row >> 7) * NCHUNK + (k >> 6);
        const int off = (row & 127) * 128 + (k & 63) * 2;
        char* dst = (char*)(isA ? Aq : Bq) + (size_t)tile * TILE_BYTES + SWZ128(off);
        *(uint4*)dst = h;
    }
    if (idx < M_TOT * B_SZ) g_rowmax[idx] = ENC_NEG;
    if (idx < B_SZ) g_i2t_den[idx] = 0.f;
    if (idx == B_SZ) g_ctr = 0;
}

// ---------------- fused HMMA GEMM + max epilogue ----------------
__global__ void __launch_bounds__(256, 2)
gemm_max_kernel(const unsigned char* __restrict__ tmask,
                const unsigned char* __restrict__ vmask)
{
    extern __shared__ char dsm[];
    __shared__ alignas(8) unsigned long long s_bar[2 * NSTAGE];
    __shared__ unsigned s_row[BM][2];
    __shared__ unsigned s_col[2][BN];
    __shared__ unsigned char s_tm[BM], s_vm[BN];

    const int tid = threadIdx.x;
    const int w = tid >> 5, lane = tid & 31;
    const int g = lane >> 2, tig = lane & 3;
    const int wm = w >> 2, wn = w & 3;

    int bid = blockIdx.x;
    int tm_i, tn_i;
    if (bid < (NT_N / PANEL_W) * NT_M * PANEL_W) {
        int p = bid >> 7, idx = bid & 127;
        tn_i = p * PANEL_W + (idx >> 5);
        tm_i = idx & 31;
    } else {
        int e = bid - (NT_N / PANEL_W) * NT_M * PANEL_W;
        tn_i = (NT_N / PANEL_W) * PANEL_W + (e >> 5);
        tm_i = e & 31;
    }
    const int m0 = tm_i * BM;
    const int n0 = tn_i * BN;

    const char* gAt = (const char*)Aq + (size_t)(tm_i * NCHUNK) * TILE_BYTES;
    const char* gBt = (const char*)Bq + (size_t)(tn_i * NCHUNK) * TILE_BYTES;
    const uint32_t smem_base = smem_u32(dsm);
    const uint32_t bar0 = smem_u32(&s_bar[0]);

    if (tid == 0) {
#pragma unroll
        for (int s = 0; s < NSTAGE; s++) {
            MBAR_INIT(bar0 + s * 8, 1);
            MBAR_INIT(bar0 + (NSTAGE + s) * 8, 8);   // per-warp elected arrives
        }
        FENCE_ASYNC();
    }
    __syncthreads();
    if (tid == 0) {
#pragma unroll
        for (int c = 0; c < NSTAGE; c++) {
            const uint32_t fb = bar0 + c * 8;
            MBAR_EXPECT_TX(fb, STAGE_BYTES);
            bulk_g2s(smem_base + c * STAGE_BYTES,              gAt + (size_t)c * TILE_BYTES, fb);
            bulk_g2s(smem_base + c * STAGE_BYTES + TILE_BYTES, gBt + (size_t)c * TILE_BYTES, fb);
        }
    }

    // ---- epilogue prep hoisted (independent of mainloop) ----
    for (int e = tid; e < BM * 2; e += 256) ((unsigned*)s_row)[e] = ENC_NEG;
    for (int e = tid; e < 2 * BN; e += 256) ((unsigned*)s_col)[e] = ENC_NEG;
    if (tid < BM) s_tm[tid] = tmask[m0 + tid];
    else          s_vm[tid - BM] = vmask[n0 + (tid - BM)];

    uint32_t rawA[4], rawB[2];
#pragma unroll
    for (int mt = 0; mt < 4; mt++)
        rawA[mt] = (wm * 64 + mt * 16 + (lane & 15)) * 128 + (lane >> 4) * 16;
#pragma unroll
    for (int ntp = 0; ntp < 2; ntp++) {
        int nrow = wn * 32 + ntp * 16 + (lane & 7) + ((lane >> 4) << 3);
        rawB[ntp] = nrow * 128 + (((lane >> 3) & 1) ? 16 : 0);
    }

    float acc[4][4][4];
#pragma unroll
    for (int mt = 0; mt < 4; mt++)
#pragma unroll
        for (int nt = 0; nt < 4; nt++)
#pragma unroll
            for (int i = 0; i < 4; i++) acc[mt][nt][i] = 0.f;

#pragma unroll 1
    for (int ch = 0; ch < NCHUNK; ch++) {
        const int s = ch % NSTAGE;
        const int grp = ch / NSTAGE;
        const uint32_t full_b  = bar0 + s * 8;
        const uint32_t empty_b = bar0 + (NSTAGE + s) * 8;

        MBAR_WAIT(full_b, grp & 1);

        const uint32_t As = smem_base + s * STAGE_BYTES;
        const uint32_t Bs = As + TILE_BYTES;
#pragma unroll
        for (int kk = 0; kk < 4; kk++) {
            uint32_t a[4][4], b[2][4];
#pragma unroll
            for (int mt = 0; mt < 4; mt++)
                ldmx4(a[mt], As + SWZ128(rawA[mt] + kk * 32));
#pragma unroll
            for (int ntp = 0; ntp < 2; ntp++)
                ldmx4(b[ntp], Bs + SWZ128(rawB[ntp] + kk * 32));
#pragma unroll
            for (int mt = 0; mt < 4; mt++) {
                mma16816(acc[mt][0], a[mt], b[0][0], b[0][1]);
                mma16816(acc[mt][1], a[mt], b[0][2], b[0][3]);
                mma16816(acc[mt][2], a[mt], b[1][0], b[1][1]);
                mma16816(acc[mt][3], a[mt], b[1][2], b[1][3]);
            }
        }

        if (ch + NSTAGE < NCHUNK) {
            // stage s is free once this warp's last ldmatrix returned;
            // ldmatrix.sync.aligned converges the warp, so lane 0 arrives for it
            if (lane == 0) MBAR_ARRIVE(empty_b);
            if (tid == 0) {
                MBAR_WAIT(empty_b, grp & 1);   // all 8 warps consumed stage s
                const int c2 = ch + NSTAGE;
                MBAR_EXPECT_TX(full_b, STAGE_BYTES);
                bulk_g2s(As, gAt + (size_t)c2 * TILE_BYTES, full_b);
                bulk_g2s(Bs, gBt + (size_t)c2 * TILE_BYTES, full_b);
            }
        }
    }

    // ---------------- fused max epilogue ----------------
    __syncthreads();   // all prep + all warps' mainloops complete

    const int y0 = n0 / I_TOK;
    const int b1 = (y0 + 1) * I_TOK - n0;

    int ncol[4][2]; bool vm_ok[4][2]; bool seg1[4][2];
#pragma unroll
    for (int nt = 0; nt < 4; nt++)
#pragma unroll
        for (int cc = 0; cc < 2; cc++) {
            int nl = wn * 32 + nt * 8 + 2 * tig + cc;
            ncol[nt][cc] = nl;
            vm_ok[nt][cc] = s_vm[nl] != 0;
            seg1[nt][cc] = nl >= b1;
        }
    int mrow[4][2]; bool tm_ok[4][2];
#pragma unroll
    for (int mt = 0; mt < 4; mt++)
#pragma unroll
        for (int gg = 0; gg < 2; gg++) {
            int ml = wm * 64 + mt * 16 + g + gg * 8;
            mrow[mt][gg] = ml;
            tm_ok[mt][gg] = s_tm[ml] != 0;
        }

#pragma unroll
    for (int mt = 0; mt < 4; mt++)
#pragma unroll
        for (int gg = 0; gg < 2; gg++) {
            float mx0 = -FLT_MAX, mx1 = -FLT_MAX;
#pragma unroll
            for (int nt = 0; nt < 4; nt++)
#pragma unroll
                for (int cc = 0; cc < 2; cc++) {
                    if (!vm_ok[nt][cc]) continue;
                    float v = acc[mt][nt][gg * 2 + cc];
                    if (seg1[nt][cc]) mx1 = fmaxf(mx1, v);
                    else              mx0 = fmaxf(mx0, v);
                }
#pragma unroll
            for (int o = 1; o <= 2; o <<= 1) {
                mx0 = fmaxf(mx0, __shfl_xor_sync(0xffffffffu, mx0, o));
                mx1 = fmaxf(mx1, __shfl_xor_sync(0xffffffffu, mx1, o));
            }
            if (tig == 0) {
                if (mx0 > -FLT_MAX) atomicMax(&s_row[mrow[mt][gg]][0], enc_f(mx0));
                if (mx1 > -FLT_MAX) atomicMax(&s_row[mrow[mt][gg]][1], enc_f(mx1));
            }
        }

    const int xh = wm;
#pragma unroll
    for (int nt = 0; nt < 4; nt++)
#pragma unroll
        for (int cc = 0; cc < 2; cc++) {
            float mx = -FLT_MAX;
#pragma unroll
            for (int mt = 0; mt < 4; mt++)
#pragma unroll
                for (int gg = 0; gg < 2; gg++)
                    if (tm_ok[mt][gg]) mx = fmaxf(mx, acc[mt][nt][gg * 2 + cc]);
#pragma unroll
            for (int o = 4; o <= 16; o <<= 1)
                mx = fmaxf(mx, __shfl_xor_sync(0xffffffffu, mx, o));
            if (g == 0 && mx > -FLT_MAX)
                atomicMax(&s_col[xh][ncol[nt][cc]], enc_f(mx));
        }
    __syncthreads();

    const int ylast = (n0 + BN - 1) / I_TOK;
    for (int e = tid; e < BM * 2; e += 256) {
        const int rr = e >> 1, seg = e & 1;
        if (y0 + seg > ylast) continue;
        const unsigned v = s_row[rr][seg];
        if (v != ENC_NEG)
            atomicMax(&g_rowmax[(size_t)(m0 + rr) * B_SZ + y0 + seg], v);
    }
    for (int e = tid; e < 2 * BN; e += 256) {
        const int hh = e >> 7, col = e & 127;
        g_colmax[(size_t)((m0 >> 6) + hh) * N_TOT + n0 + col] = dec_f(s_col[hh][col]);
    }
}

// ---------------- means + finalize (last-block trick) ----------------
__global__ void means_kernel(const unsigned char* __restrict__ tmask,
                             const unsigned char* __restrict__ vmask,
                             float* __restrict__ out)
{
    __shared__ float sh_e1[B_SZ];
    __shared__ float sh_red[2][2];
    __shared__ int s_last;
    const int x = blockIdx.x;
    const int tid = threadIdx.x;          // 256
    const int y = tid >> 2, q = tid & 3;
    const float temp = expf(logf((float)(1.0 / 0.07)));

    float s2 = 0.f, c2 = 0.f;
    for (int i = q; i < I_TOK; i += 4) {
        if (vmask[y * I_TOK + i]) {
            s2 += g_colmax[(size_t)x * N_TOT + y * I_TOK + i];
            c2 += 1.f;
        }
    }
    float s1 = 0.f, c1 = 0.f;
    for (int t = q; t < B_SZ; t += 4) {
        if (tmask[x * B_SZ + t]) {
            s1 += dec_f(g_rowmax[(size_t)(x * B_SZ + t) * B_SZ + y]);
            c1 += 1.f;
        }
    }
#pragma unroll
    for (int o = 1; o <= 2; o <<= 1) {
        s1 += __shfl_xor_sync(0xffffffffu, s1, o);
        c1 += __shfl_xor_sync(0xffffffffu, c1, o);
        s2 += __shfl_xor_sync(0xffffffffu, s2, o);
        c2 += __shfl_xor_sync(0xffffffffu, c2, o);
    }
    if (q == 0) {
        const float t2i = temp * (s1 / fmaxf(c1, 1e-6f));
        const float i2t = temp * (s2 / fmaxf(c2, 1e-6f));
        const float e1 = expf(t2i), e2 = expf(i2t);
        sh_e1[y] = e1;
        atomicAdd(&g_i2t_den[y], e2);
        if (y == x) { g_d1[x] = e1; g_d2[x] = e2; }
    }
    __syncthreads();
    if (tid == 0) {
        float acc = 0.f;
        for (int k = 0; k < B_SZ; k++) acc += sh_e1[k];
        g_t2i_den[x] = acc;
        __threadfence();
        s_last = (atomicAdd(&g_ctr, 1) == B_SZ - 1);
    }
    __syncthreads();
    if (!s_last) return;
    __threadfence();

    float l1 = 0.f, l2 = 0.f;
    if (tid < B_SZ) {
        l1 = -logf(g_d1[tid] + 1e-20f) + logf(g_t2i_den[tid] + 1e-20f);
        l2 = -logf(g_d2[tid] + 1e-20f) + logf(g_i2t_den[tid] + 1e-20f);
#pragma unroll
        for (int o = 16; o > 0; o >>= 1) {
            l1 += __shfl_xor_sync(0xffffffffu, l1, o);
            l2 += __shfl_xor_sync(0xffffffffu, l2, o);
        }
        if ((tid & 31) == 0) { sh_red[0][tid >> 5] = l1; sh_red[1][tid >> 5] = l2; }
    }
    __syncthreads();
    if (tid == 0) {
        float a = (sh_red[0][0] + sh_red[0][1]) * (1.f / 64.f);
        float b = (sh_red[1][0] + sh_red[1][1]) * (1.f / 64.f);
        out[0] = 0.5f * (a + b);
        out[1] = a;
        out[2] = b;
    }
}

extern "C" void kernel_launch(void* const* d_in, const int* in_sizes, int n_in,
                              void* d_out, int out_size)
{
    const float *vision, *text;
    const unsigned char *vmask, *tmask;
    if (in_sizes[0] == N_TOT * D_K) {
        vision = (const float*)d_in[0];
        text   = (const float*)d_in[1];
    } else {
        vision = (const float*)d_in[1];
        text   = (const float*)d_in[0];
    }
    if (in_sizes[2] == N_TOT) {
        vmask = (const unsigned char*)d_in[2];
        tmask = (const unsigned char*)d_in[3];
    } else {
        vmask = (const unsigned char*)d_in[3];
        tmask = (const unsigned char*)d_in[2];
    }
    float* out = (float*)d_out;

    cudaFuncSetAttribute(gemm_max_kernel,
                         cudaFuncAttributeMaxDynamicSharedMemorySize, DSMEM_BYTES);

    const int groups = (M_TOT + N_TOT) * D_K / 8;
    convert_kernel<<<(groups + 255) / 256, 256>>>(text, vision);
    gemm_max_kernel<<<NT_M * NT_N, 256, DSMEM_BYTES>>>(tmask, vmask);
    means_kernel<<<B_SZ, 256>>>(tmask, vmask, out);
}

// round 15
// speedup vs baseline: 1.0126x; 1.0126x over previous
#include <cuda_runtime.h>
#include <cuda_fp16.h>
#include <math.h>
#include <float.h>
#include <stdint.h>
#include <string.h>

// FILIP loss. B=64, T=64, I=196, D=512.
// sim = text[4096,512] @ vision[12544,512]^T with fused row/col max epilogue.
// fp16 HMMA GEMM (champion config). i2t column-max sums fused directly into
// the GEMM epilogue (g_colmax eliminated: each (x,n) colmax has exactly one
// writer CTA, so partial masked sums can be atomicAdd'ed at tile end).

#define D_K   512
#define M_TOT 4096
#define N_TOT 12544
#define B_SZ  64
#define I_TOK 196

#define BM 128
#define BN 128
#define BK 64
#define NCHUNK (D_K / BK)            // 8
#define NSTAGE 3
#define TILE_BYTES 16384
#define STAGE_BYTES (2 * TILE_BYTES)
#define DSMEM_BYTES (NSTAGE * STAGE_BYTES)   // 98304 -> 2 CTAs/SM

#define NT_M (M_TOT / BM)            // 32
#define NT_N (N_TOT / BN)            // 98
#define PANEL_W 4

#define ENC_NEG 0x00800000u
#define SWZ128(o) ((o) ^ (((o) >> 3) & 0x70))

__device__ __forceinline__ uint32_t smem_u32(const void* p) {
    uint32_t a;
    asm("{ .reg .u64 t; cvta.to.shared.u64 t, %1; cvt.u32.u64 %0, t; }" : "=r"(a) : "l"(p));
    return a;
}
__device__ __forceinline__ uint32_t h2_u32(half2 h) {
    uint32_t u; memcpy(&u, &h, 4); return u;
}
__device__ __forceinline__ unsigned enc_f(float f) {
    unsigned u = __float_as_uint(f);
    return (u & 0x80000000u) ? ~u : (u | 0x80000000u);
}
__device__ __forceinline__ float dec_f(unsigned u) {
    return __uint_as_float((u & 0x80000000u) ? (u & 0x7FFFFFFFu) : ~u);
}

#define MBAR_INIT(mb, c) asm volatile("mbarrier.init.shared.b64 [%0], %1;" :: "r"(mb), "r"(c) : "memory")
#define MBAR_ARRIVE(mb)  asm volatile("mbarrier.arrive.shared.b64 _, [%0];" :: "r"(mb) : "memory")
#define MBAR_EXPECT_TX(mb, n) asm volatile("mbarrier.arrive.expect_tx.shared.b64 _, [%0], %1;" :: "r"(mb), "r"(n) : "memory")
#define FENCE_ASYNC() asm volatile("fence.proxy.async.shared::cta;" ::: "memory")

#define MBAR_WAIT(mb, par) do { \
    uint32_t _m = (mb), _p = (par), _d; \
    asm volatile("{ .reg .pred p; mbarrier.try_wait.parity.acquire.cta.shared::cta.b64 p, [%1], %2; selp.b32 %0,1,0,p; }" \
        : "=r"(_d) : "r"(_m), "r"(_p) : "memory"); \
    if (!_d) { \
        asm volatile("{ .reg .pred P1; WL_%=: mbarrier.try_wait.parity.acquire.cta.shared::cta.b64 P1, [%0], %1, 0x989680; @P1 bra.uni WD_%=; bra.uni WL_%=; WD_%=: }" \
            :: "r"(_m), "r"(_p) : "memory"); \
    } } while (0)

__device__ __forceinline__ void bulk_g2s(uint32_t dst, const void* src, uint32_t mb) {
    asm volatile("cp.async.bulk.shared::cluster.global.mbarrier::complete_tx::bytes [%0], [%1], %2, [%3];"
        :: "r"(dst), "l"(__cvta_generic_to_global(src)), "r"((uint32_t)TILE_BYTES), "r"(mb) : "memory");
}
__device__ __forceinline__ void ldmx4(uint32_t* r, uint32_t addr) {
    asm volatile("ldmatrix.sync.aligned.m8n8.x4.shared.b16 {%0,%1,%2,%3}, [%4];"
        : "=r"(r[0]), "=r"(r[1]), "=r"(r[2]), "=r"(r[3]) : "r"(addr));
}
__device__ __forceinline__ void mma16816(float* c, const uint32_t* a, uint32_t b0, uint32_t b1) {
    asm volatile("mma.sync.aligned.m16n8k16.row.col.f32.f16.f16.f32 "
        "{%0,%1,%2,%3}, {%4,%5,%6,%7}, {%8,%9}, {%0,%1,%2,%3};"
        : "+f"(c[0]), "+f"(c[1]), "+f"(c[2]), "+f"(c[3])
        : "r"(a[0]), "r"(a[1]), "r"(a[2]), "r"(a[3]), "r"(b0), "r"(b1));
}

// ---------------- scratch ----------------
__device__ __half  Aq[(size_t)M_TOT * D_K];   // tiled+SW128: tile=(rowblk*8+ch)
__device__ __half  Bq[(size_t)N_TOT * D_K];
__device__ unsigned g_rowmax[M_TOT * B_SZ];
__device__ float    g_i2t_sum[B_SZ * B_SZ];   // masked colmax sums per (x,y)
__device__ float    g_t2i_den[B_SZ], g_i2t_den[B_SZ];
__device__ float    g_d1[B_SZ], g_d2[B_SZ];
__device__ int      g_ctr;

// convert (fp32 -> fp16, tiled + SW128 swizzled, 8 elems/thread) + init, fused
__global__ void convert_kernel(const float* __restrict__ text,
                               const float* __restrict__ vision) {
    const int TG = M_TOT * D_K / 8;
    const int VG = N_TOT * D_K / 8;
    int idx = blockIdx.x * blockDim.x + threadIdx.x;
    if (idx < TG + VG) {
        const bool isA = idx < TG;
        const int p = isA ? idx : idx - TG;
        const int row = p >> 6;
        const int k = (p & 63) << 3;
        const float* src = (isA ? text : vision) + (size_t)row * D_K + k;
        float4 v0 = *(const float4*)(src);
        float4 v1 = *(const float4*)(src + 4);
        uint4 h;
        h.x = h2_u32(__floats2half2_rn(v0.x, v0.y));
        h.y = h2_u32(__floats2half2_rn(v0.z, v0.w));
        h.z = h2_u32(__floats2half2_rn(v1.x, v1.y));
        h.w = h2_u32(__floats2half2_rn(v1.z, v1.w));
        const int tile = (row >> 7) * NCHUNK + (k >> 6);
        const int off = (row & 127) * 128 + (k & 63) * 2;
        char* dst = (char*)(isA ? Aq : Bq) + (size_t)tile * TILE_BYTES + SWZ128(off);
        *(uint4*)dst = h;
    }
    if (idx < M_TOT * B_SZ) g_rowmax[idx] = ENC_NEG;
    if (idx < B_SZ * B_SZ) g_i2t_sum[idx] = 0.f;
    if (idx < B_SZ) g_i2t_den[idx] = 0.f;
    if (idx == B_SZ) g_ctr = 0;
}

// ---------------- fused HMMA GEMM + max epilogue ----------------
__global__ void __launch_bounds__(256, 2)
gemm_max_kernel(const unsigned char* __restrict__ tmask,
                const unsigned char* __restrict__ vmask)
{
    extern __shared__ char dsm[];
    __shared__ alignas(8) unsigned long long s_bar[2 * NSTAGE];
    __shared__ unsigned s_row[BM][2];
    __shared__ unsigned char s_tm[BM], s_vm[BN];

    const int tid = threadIdx.x;
    const int w = tid >> 5, lane = tid & 31;
    const int g = lane >> 2, tig = lane & 3;
    const int wm = w >> 2, wn = w & 3;

    int bid = blockIdx.x;
    int tm_i, tn_i;
    if (bid < (NT_N / PANEL_W) * NT_M * PANEL_W) {
        int p = bid >> 7, idx = bid & 127;
        tn_i = p * PANEL_W + (idx >> 5);
        tm_i = idx & 31;
    } else {
        int e = bid - (NT_N / PANEL_W) * NT_M * PANEL_W;
        tn_i = (NT_N / PANEL_W) * PANEL_W + (e >> 5);
        tm_i = e & 31;
    }
    const int m0 = tm_i * BM;
    const int n0 = tn_i * BN;

    const char* gAt = (const char*)Aq + (size_t)(tm_i * NCHUNK) * TILE_BYTES;
    const char* gBt = (const char*)Bq + (size_t)(tn_i * NCHUNK) * TILE_BYTES;
    const uint32_t smem_base = smem_u32(dsm);
    const uint32_t bar0 = smem_u32(&s_bar[0]);

    if (tid == 0) {
#pragma unroll
        for (int s = 0; s < NSTAGE; s++) {
            MBAR_INIT(bar0 + s * 8, 1);
            MBAR_INIT(bar0 + (NSTAGE + s) * 8, 8);   // per-warp elected arrives
        }
        FENCE_ASYNC();
    }
    __syncthreads();
    if (tid == 0) {
#pragma unroll
        for (int c = 0; c < NSTAGE; c++) {
            const uint32_t fb = bar0 + c * 8;
            MBAR_EXPECT_TX(fb, STAGE_BYTES);
            bulk_g2s(smem_base + c * STAGE_BYTES,              gAt + (size_t)c * TILE_BYTES, fb);
            bulk_g2s(smem_base + c * STAGE_BYTES + TILE_BYTES, gBt + (size_t)c * TILE_BYTES, fb);
        }
    }

    // ---- epilogue prep hoisted (independent of mainloop) ----
    for (int e = tid; e < BM * 2; e += 256) ((unsigned*)s_row)[e] = ENC_NEG;
    if (tid < BM) s_tm[tid] = tmask[m0 + tid];
    else          s_vm[tid - BM] = vmask[n0 + (tid - BM)];

    uint32_t rawA[4], rawB[2];
#pragma unroll
    for (int mt = 0; mt < 4; mt++)
        rawA[mt] = (wm * 64 + mt * 16 + (lane & 15)) * 128 + (lane >> 4) * 16;
#pragma unroll
    for (int ntp = 0; ntp < 2; ntp++) {
        int nrow = wn * 32 + ntp * 16 + (lane & 7) + ((lane >> 4) << 3);
        rawB[ntp] = nrow * 128 + (((lane >> 3) & 1) ? 16 : 0);
    }

    float acc[4][4][4];
#pragma unroll
    for (int mt = 0; mt < 4; mt++)
#pragma unroll
        for (int nt = 0; nt < 4; nt++)
#pragma unroll
            for (int i = 0; i < 4; i++) acc[mt][nt][i] = 0.f;

#pragma unroll 1
    for (int ch = 0; ch < NCHUNK; ch++) {
        const int s = ch % NSTAGE;
        const int grp = ch / NSTAGE;
        const uint32_t full_b  = bar0 + s * 8;
        const uint32_t empty_b = bar0 + (NSTAGE + s) * 8;

        MBAR_WAIT(full_b, grp & 1);

        const uint32_t As = smem_base + s * STAGE_BYTES;
        const uint32_t Bs = As + TILE_BYTES;
#pragma unroll
        for (int kk = 0; kk < 4; kk++) {
            uint32_t a[4][4], b[2][4];
#pragma unroll
            for (int mt = 0; mt < 4; mt++)
                ldmx4(a[mt], As + SWZ128(rawA[mt] + kk * 32));
#pragma unroll
            for (int ntp = 0; ntp < 2; ntp++)
                ldmx4(b[ntp], Bs + SWZ128(rawB[ntp] + kk * 32));
#pragma unroll
            for (int mt = 0; mt < 4; mt++) {
                mma16816(acc[mt][0], a[mt], b[0][0], b[0][1]);
                mma16816(acc[mt][1], a[mt], b[0][2], b[0][3]);
                mma16816(acc[mt][2], a[mt], b[1][0], b[1][1]);
                mma16816(acc[mt][3], a[mt], b[1][2], b[1][3]);
            }
        }

        if (ch + NSTAGE < NCHUNK) {
            if (lane == 0) MBAR_ARRIVE(empty_b);
            if (tid == 0) {
                MBAR_WAIT(empty_b, grp & 1);
                const int c2 = ch + NSTAGE;
                MBAR_EXPECT_TX(full_b, STAGE_BYTES);
                bulk_g2s(As, gAt + (size_t)c2 * TILE_BYTES, full_b);
                bulk_g2s(Bs, gBt + (size_t)c2 * TILE_BYTES, full_b);
            }
        }
    }

    // ---------------- fused max epilogue ----------------
    __syncthreads();   // all prep + all warps' mainloops complete

    const int y0 = n0 / I_TOK;
    const int b1 = (y0 + 1) * I_TOK - n0;
    const int ylast = (n0 + BN - 1) / I_TOK;

    bool vm_ok[4][2]; bool seg1[4][2];
#pragma unroll
    for (int nt = 0; nt < 4; nt++)
#pragma unroll
        for (int cc = 0; cc < 2; cc++) {
            int nl = wn * 32 + nt * 8 + 2 * tig + cc;
            vm_ok[nt][cc] = s_vm[nl] != 0;
            seg1[nt][cc] = nl >= b1;
        }
    int mrow[4][2]; bool tm_ok[4][2];
#pragma unroll
    for (int mt = 0; mt < 4; mt++)
#pragma unroll
        for (int gg = 0; gg < 2; gg++) {
            int ml = wm * 64 + mt * 16 + g + gg * 8;
            mrow[mt][gg] = ml;
            tm_ok[mt][gg] = s_tm[ml] != 0;
        }

    // rowmax: per (mt,gg) per seg, reduce across quad (cols), lane tig==0 atomics
#pragma unroll
    for (int mt = 0; mt < 4; mt++)
#pragma unroll
        for (int gg = 0; gg < 2; gg++) {
            float mx0 = -FLT_MAX, mx1 = -FLT_MAX;
#pragma unroll
            for (int nt = 0; nt < 4; nt++)
#pragma unroll
                for (int cc = 0; cc < 2; cc++) {
                    if (!vm_ok[nt][cc]) continue;
                    float v = acc[mt][nt][gg * 2 + cc];
                    if (seg1[nt][cc]) mx1 = fmaxf(mx1, v);
                    else              mx0 = fmaxf(mx0, v);
                }
#pragma unroll
            for (int o = 1; o <= 2; o <<= 1) {
                mx0 = fmaxf(mx0, __shfl_xor_sync(0xffffffffu, mx0, o));
                mx1 = fmaxf(mx1, __shfl_xor_sync(0xffffffffu, mx1, o));
            }
            if (tig == 0) {
                if (mx0 > -FLT_MAX) atomicMax(&s_row[mrow[mt][gg]][0], enc_f(mx0));
                if (mx1 > -FLT_MAX) atomicMax(&s_row[mrow[mt][gg]][1], enc_f(mx1));
            }
        }

    // colmax + fused i2t partial sums. Each warp owns (x-half wm, cols wn*32..+31)
    // exclusively -> compute masked column-max, then masked sum per y-segment,
    // atomicAdd into g_i2t_sum. No smem stage, no g_colmax.
    {
        float sum0 = 0.f, sum1 = 0.f;
#pragma unroll
        for (int nt = 0; nt < 4; nt++)
#pragma unroll
            for (int cc = 0; cc < 2; cc++) {
                float mx = -FLT_MAX;
#pragma unroll
                for (int mt = 0; mt < 4; mt++)
#pragma unroll
                    for (int gg = 0; gg < 2; gg++)
                        if (tm_ok[mt][gg]) mx = fmaxf(mx, acc[mt][nt][gg * 2 + cc]);
#pragma unroll
                for (int o = 4; o <= 16; o <<= 1)
                    mx = fmaxf(mx, __shfl_xor_sync(0xffffffffu, mx, o));
                // all lanes now hold colmax for col(nt,cc,tig); lanes g==0 accumulate
                if (g == 0 && vm_ok[nt][cc]) {
                    if (seg1[nt][cc]) sum1 += mx;
                    else              sum0 += mx;
                }
            }
        // combine over tig (lanes 0..3 hold partials; others hold 0)
#pragma unroll
        for (int o = 1; o <= 2; o <<= 1) {
            sum0 += __shfl_xor_sync(0xffffffffu, sum0, o);
            sum1 += __shfl_xor_sync(0xffffffffu, sum1, o);
        }
        if (lane == 0) {
            const int x = (m0 >> 6) + wm;
            atomicAdd(&g_i2t_sum[x * B_SZ + y0], sum0);
            if (y0 + 1 <= ylast) atomicAdd(&g_i2t_sum[x * B_SZ + y0 + 1], sum1);
        }
    }
    __syncthreads();

    // flush rowmax to global
    for (int e = tid; e < BM * 2; e += 256) {
        const int rr = e >> 1, seg = e & 1;
        if (y0 + seg > ylast) continue;
        const unsigned v = s_row[rr][seg];
        if (v != ENC_NEG)
            atomicMax(&g_rowmax[(size_t)(m0 + rr) * B_SZ + y0 + seg], v);
    }
}

// ---------------- means + finalize (last-block trick) ----------------
__global__ void means_kernel(const unsigned char* __restrict__ tmask,
                             const unsigned char* __restrict__ vmask,
                             float* __restrict__ out)
{
    __shared__ float sh_e1[B_SZ];
    __shared__ float sh_red[2][2];
    __shared__ int s_last;
    const int x = blockIdx.x;
    const int tid = threadIdx.x;          // 256
    const int y = tid >> 2, q = tid & 3;
    const float temp = expf(logf((float)(1.0 / 0.07)));

    // i2t count (sum comes pre-reduced from the GEMM epilogue)
    float c2 = 0.f;
    for (int i = q; i < I_TOK; i += 4)
        c2 += vmask[y * I_TOK + i] ? 1.f : 0.f;
    // t2i: mean over t of rowmax[(x*64+t)][y]
    float s1 = 0.f, c1 = 0.f;
    for (int t = q; t < B_SZ; t += 4) {
        if (tmask[x * B_SZ + t]) {
            s1 += dec_f(g_rowmax[(size_t)(x * B_SZ + t) * B_SZ + y]);
            c1 += 1.f;
        }
    }
#pragma unroll
    for (int o = 1; o <= 2; o <<= 1) {
        s1 += __shfl_xor_sync(0xffffffffu, s1, o);
        c1 += __shfl_xor_sync(0xffffffffu, c1, o);
        c2 += __shfl_xor_sync(0xffffffffu, c2, o);
    }
    if (q == 0) {
        const float t2i = temp * (s1 / fmaxf(c1, 1e-6f));
        const float i2t = temp * (g_i2t_sum[x * B_SZ + y] / fmaxf(c2, 1e-6f));
        const float e1 = expf(t2i), e2 = expf(i2t);
        sh_e1[y] = e1;
        atomicAdd(&g_i2t_den[y], e2);
        if (y == x) { g_d1[x] = e1; g_d2[x] = e2; }
    }
    __syncthreads();
    if (tid == 0) {
        float acc = 0.f;
        for (int k = 0; k < B_SZ; k++) acc += sh_e1[k];
        g_t2i_den[x] = acc;
        __threadfence();
        s_last = (atomicAdd(&g_ctr, 1) == B_SZ - 1);
    }
    __syncthreads();
    if (!s_last) return;
    __threadfence();

    float l1 = 0.f, l2 = 0.f;
    if (tid < B_SZ) {
        l1 = -logf(g_d1[tid] + 1e-20f) + logf(g_t2i_den[tid] + 1e-20f);
        l2 = -logf(g_d2[tid] + 1e-20f) + logf(g_i2t_den[tid] + 1e-20f);
#pragma unroll
        for (int o = 16; o > 0; o >>= 1) {
            l1 += __shfl_xor_sync(0xffffffffu, l1, o);
            l2 += __shfl_xor_sync(0xffffffffu, l2, o);
        }
        if ((tid & 31) == 0) { sh_red[0][tid >> 5] = l1; sh_red[1][tid >> 5] = l2; }
    }
    __syncthreads();
    if (tid == 0) {
        float a = (sh_red[0][0] + sh_red[0][1]) * (1.f / 64.f);
        float b = (sh_red[1][0] + sh_red[1][1]) * (1.f / 64.f);
        out[0] = 0.5f * (a + b);
        out[1] = a;
        out[2] = b;
    }
}

extern "C" void kernel_launch(void* const* d_in, const int* in_sizes, int n_in,
                              void* d_out, int out_size)
{
    const float *vision, *text;
    const unsigned char *vmask, *tmask;
    if (in_sizes[0] == N_TOT * D_K) {
        vision = (const float*)d_in[0];
        text   = (const float*)d_in[1];
    } else {
        vision = (const float*)d_in[1];
        text   = (const float*)d_in[0];
    }
    if (in_sizes[2] == N_TOT) {
        vmask = (const unsigned char*)d_in[2];
        tmask = (const unsigned char*)d_in[3];
    } else {
        vmask = (const unsigned char*)d_in[3];
        tmask = (const unsigned char*)d_in[2];
    }
    float* out = (float*)d_out;

    cudaFuncSetAttribute(gemm_max_kernel,
                         cudaFuncAttributeMaxDynamicSharedMemorySize, DSMEM_BYTES);

    const int groups = (M_TOT + N_TOT) * D_K / 8;
    convert_kernel<<<(groups + 255) / 256, 256>>>(text, vision);
    gemm_max_kernel<<<NT_M * NT_N, 256, DSMEM_BYTES>>>(tmask, vmask);
    means_kernel<<<B_SZ, 256>>>(tmask, vmask, out);
}

// round 16
// speedup vs baseline: 1.0147x; 1.0020x over previous
#include <cuda_runtime.h>
#include <cuda_fp16.h>
#include <math.h>
#include <float.h>
#include <stdint.h>
#include <string.h>

// FILIP loss. B=64, T=64, I=196, D=512.
// sim = text[4096,512] @ vision[12544,512]^T with fused row/col max epilogue.
// fp16 HMMA GEMM (champion config). i2t sums fused into GEMM epilogue.
// means_kernel rebuilt with coalesced g_rowmax access (t-group x y layout).

#define D_K   512
#define M_TOT 4096
#define N_TOT 12544
#define B_SZ  64
#define I_TOK 196

#define BM 128
#define BN 128
#define BK 64
#define NCHUNK (D_K / BK)            // 8
#define NSTAGE 3
#define TILE_BYTES 16384
#define STAGE_BYTES (2 * TILE_BYTES)
#define DSMEM_BYTES (NSTAGE * STAGE_BYTES)   // 98304 -> 2 CTAs/SM

#define NT_M (M_TOT / BM)            // 32
#define NT_N (N_TOT / BN)            // 98
#define PANEL_W 4

#define ENC_NEG 0x00800000u
#define SWZ128(o) ((o) ^ (((o) >> 3) & 0x70))

__device__ __forceinline__ uint32_t smem_u32(const void* p) {
    uint32_t a;
    asm("{ .reg .u64 t; cvta.to.shared.u64 t, %1; cvt.u32.u64 %0, t; }" : "=r"(a) : "l"(p));
    return a;
}
__device__ __forceinline__ uint32_t h2_u32(half2 h) {
    uint32_t u; memcpy(&u, &h, 4); return u;
}
__device__ __forceinline__ unsigned enc_f(float f) {
    unsigned u = __float_as_uint(f);
    return (u & 0x80000000u) ? ~u : (u | 0x80000000u);
}
__device__ __forceinline__ float dec_f(unsigned u) {
    return __uint_as_float((u & 0x80000000u) ? (u & 0x7FFFFFFFu) : ~u);
}

#define MBAR_INIT(mb, c) asm volatile("mbarrier.init.shared.b64 [%0], %1;" :: "r"(mb), "r"(c) : "memory")
#define MBAR_ARRIVE(mb)  asm volatile("mbarrier.arrive.shared.b64 _, [%0];" :: "r"(mb) : "memory")
#define MBAR_EXPECT_TX(mb, n) asm volatile("mbarrier.arrive.expect_tx.shared.b64 _, [%0], %1;" :: "r"(mb), "r"(n) : "memory")
#define FENCE_ASYNC() asm volatile("fence.proxy.async.shared::cta;" ::: "memory")

#define MBAR_WAIT(mb, par) do { \
    uint32_t _m = (mb), _p = (par), _d; \
    asm volatile("{ .reg .pred p; mbarrier.try_wait.parity.acquire.cta.shared::cta.b64 p, [%1], %2; selp.b32 %0,1,0,p; }" \
        : "=r"(_d) : "r"(_m), "r"(_p) : "memory"); \
    if (!_d) { \
        asm volatile("{ .reg .pred P1; WL_%=: mbarrier.try_wait.parity.acquire.cta.shared::cta.b64 P1, [%0], %1, 0x989680; @P1 bra.uni WD_%=; bra.uni WL_%=; WD_%=: }" \
            :: "r"(_m), "r"(_p) : "memory"); \
    } } while (0)

__device__ __forceinline__ void bulk_g2s(uint32_t dst, const void* src, uint32_t mb) {
    asm volatile("cp.async.bulk.shared::cluster.global.mbarrier::complete_tx::bytes [%0], [%1], %2, [%3];"
        :: "r"(dst), "l"(__cvta_generic_to_global(src)), "r"((uint32_t)TILE_BYTES), "r"(mb) : "memory");
}
__device__ __forceinline__ void ldmx4(uint32_t* r, uint32_t addr) {
    asm volatile("ldmatrix.sync.aligned.m8n8.x4.shared.b16 {%0,%1,%2,%3}, [%4];"
        : "=r"(r[0]), "=r"(r[1]), "=r"(r[2]), "=r"(r[3]) : "r"(addr));
}
__device__ __forceinline__ void mma16816(float* c, const uint32_t* a, uint32_t b0, uint32_t b1) {
    asm volatile("mma.sync.aligned.m16n8k16.row.col.f32.f16.f16.f32 "
        "{%0,%1,%2,%3}, {%4,%5,%6,%7}, {%8,%9}, {%0,%1,%2,%3};"
        : "+f"(c[0]), "+f"(c[1]), "+f"(c[2]), "+f"(c[3])
        : "r"(a[0]), "r"(a[1]), "r"(a[2]), "r"(a[3]), "r"(b0), "r"(b1));
}

// ---------------- scratch ----------------
__device__ __half  Aq[(size_t)M_TOT * D_K];   // tiled+SW128: tile=(rowblk*8+ch)
__device__ __half  Bq[(size_t)N_TOT * D_K];
__device__ unsigned g_rowmax[M_TOT * B_SZ];
__device__ float    g_i2t_sum[B_SZ * B_SZ];   // masked colmax sums per (x,y)
__device__ float    g_t2i_den[B_SZ], g_i2t_den[B_SZ];
__device__ float    g_d1[B_SZ], g_d2[B_SZ];
__device__ int      g_ctr;

// convert (fp32 -> fp16, tiled + SW128 swizzled, 8 elems/thread) + init, fused
__global__ void convert_kernel(const float* __restrict__ text,
                               const float* __restrict__ vision) {
    const int TG = M_TOT * D_K / 8;
    const int VG = N_TOT * D_K / 8;
    int idx = blockIdx.x * blockDim.x + threadIdx.x;
    if (idx < TG + VG) {
        const bool isA = idx < TG;
        const int p = isA ? idx : idx - TG;
        const int row = p >> 6;
        const int k = (p & 63) << 3;
        const float* src = (isA ? text : vision) + (size_t)row * D_K + k;
        float4 v0 = *(const float4*)(src);
        float4 v1 = *(const float4*)(src + 4);
        uint4 h;
        h.x = h2_u32(__floats2half2_rn(v0.x, v0.y));
        h.y = h2_u32(__floats2half2_rn(v0.z, v0.w));
        h.z = h2_u32(__floats2half2_rn(v1.x, v1.y));
        h.w = h2_u32(__floats2half2_rn(v1.z, v1.w));
        const int tile = (row >> 7) * NCHUNK + (k >> 6);
        const int off = (row & 127) * 128 + (k & 63) * 2;
        char* dst = (char*)(isA ? Aq : Bq) + (size_t)tile * TILE_BYTES + SWZ128(off);
        *(uint4*)dst = h;
    }
    if (idx < M_TOT * B_SZ) g_rowmax[idx] = ENC_NEG;
    if (idx < B_SZ * B_SZ) g_i2t_sum[idx] = 0.f;
    if (idx < B_SZ) g_i2t_den[idx] = 0.f;
    if (idx == B_SZ) g_ctr = 0;
}

// ---------------- fused HMMA GEMM + max epilogue ----------------
__global__ void __launch_bounds__(256, 2)
gemm_max_kernel(const unsigned char* __restrict__ tmask,
                const unsigned char* __restrict__ vmask)
{
    extern __shared__ char dsm[];
    __shared__ alignas(8) unsigned long long s_bar[2 * NSTAGE];
    __shared__ unsigned s_row[BM][2];
    __shared__ unsigned char s_tm[BM], s_vm[BN];

    const int tid = threadIdx.x;
    const int w = tid >> 5, lane = tid & 31;
    const int g = lane >> 2, tig = lane & 3;
    const int wm = w >> 2, wn = w & 3;

    int bid = blockIdx.x;
    int tm_i, tn_i;
    if (bid < (NT_N / PANEL_W) * NT_M * PANEL_W) {
        int p = bid >> 7, idx = bid & 127;
        tn_i = p * PANEL_W + (idx >> 5);
        tm_i = idx & 31;
    } else {
        int e = bid - (NT_N / PANEL_W) * NT_M * PANEL_W;
        tn_i = (NT_N / PANEL_W) * PANEL_W + (e >> 5);
        tm_i = e & 31;
    }
    const int m0 = tm_i * BM;
    const int n0 = tn_i * BN;

    const char* gAt = (const char*)Aq + (size_t)(tm_i * NCHUNK) * TILE_BYTES;
    const char* gBt = (const char*)Bq + (size_t)(tn_i * NCHUNK) * TILE_BYTES;
    const uint32_t smem_base = smem_u32(dsm);
    const uint32_t bar0 = smem_u32(&s_bar[0]);

    if (tid == 0) {
#pragma unroll
        for (int s = 0; s < NSTAGE; s++) {
            MBAR_INIT(bar0 + s * 8, 1);
            MBAR_INIT(bar0 + (NSTAGE + s) * 8, 8);   // per-warp elected arrives
        }
        FENCE_ASYNC();
    }
    __syncthreads();
    if (tid == 0) {
#pragma unroll
        for (int c = 0; c < NSTAGE; c++) {
            const uint32_t fb = bar0 + c * 8;
            MBAR_EXPECT_TX(fb, STAGE_BYTES);
            bulk_g2s(smem_base + c * STAGE_BYTES,              gAt + (size_t)c * TILE_BYTES, fb);
            bulk_g2s(smem_base + c * STAGE_BYTES + TILE_BYTES, gBt + (size_t)c * TILE_BYTES, fb);
        }
    }

    // ---- epilogue prep hoisted (independent of mainloop) ----
    for (int e = tid; e < BM * 2; e += 256) ((unsigned*)s_row)[e] = ENC_NEG;
    if (tid < BM) s_tm[tid] = tmask[m0 + tid];
    else          s_vm[tid - BM] = vmask[n0 + (tid - BM)];

    uint32_t rawA[4], rawB[2];
#pragma unroll
    for (int mt = 0; mt < 4; mt++)
        rawA[mt] = (wm * 64 + mt * 16 + (lane & 15)) * 128 + (lane >> 4) * 16;
#pragma unroll
    for (int ntp = 0; ntp < 2; ntp++) {
        int nrow = wn * 32 + ntp * 16 + (lane & 7) + ((lane >> 4) << 3);
        rawB[ntp] = nrow * 128 + (((lane >> 3) & 1) ? 16 : 0);
    }

    float acc[4][4][4];
#pragma unroll
    for (int mt = 0; mt < 4; mt++)
#pragma unroll
        for (int nt = 0; nt < 4; nt++)
#pragma unroll
            for (int i = 0; i < 4; i++) acc[mt][nt][i] = 0.f;

#pragma unroll 1
    for (int ch = 0; ch < NCHUNK; ch++) {
        const int s = ch % NSTAGE;
        const int grp = ch / NSTAGE;
        const uint32_t full_b  = bar0 + s * 8;
        const uint32_t empty_b = bar0 + (NSTAGE + s) * 8;

        MBAR_WAIT(full_b, grp & 1);

        const uint32_t As = smem_base + s * STAGE_BYTES;
        const uint32_t Bs = As + TILE_BYTES;
#pragma unroll
        for (int kk = 0; kk < 4; kk++) {
            uint32_t a[4][4], b[2][4];
#pragma unroll
            for (int mt = 0; mt < 4; mt++)
                ldmx4(a[mt], As + SWZ128(rawA[mt] + kk * 32));
#pragma unroll
            for (int ntp = 0; ntp < 2; ntp++)
                ldmx4(b[ntp], Bs + SWZ128(rawB[ntp] + kk * 32));
#pragma unroll
            for (int mt = 0; mt < 4; mt++) {
                mma16816(acc[mt][0], a[mt], b[0][0], b[0][1]);
                mma16816(acc[mt][1], a[mt], b[0][2], b[0][3]);
                mma16816(acc[mt][2], a[mt], b[1][0], b[1][1]);
                mma16816(acc[mt][3], a[mt], b[1][2], b[1][3]);
            }
        }

        if (ch + NSTAGE < NCHUNK) {
            if (lane == 0) MBAR_ARRIVE(empty_b);
            if (tid == 0) {
                MBAR_WAIT(empty_b, grp & 1);
                const int c2 = ch + NSTAGE;
                MBAR_EXPECT_TX(full_b, STAGE_BYTES);
                bulk_g2s(As, gAt + (size_t)c2 * TILE_BYTES, full_b);
                bulk_g2s(Bs, gBt + (size_t)c2 * TILE_BYTES, full_b);
            }
        }
    }

    // ---------------- fused max epilogue ----------------
    __syncthreads();   // all prep + all warps' mainloops complete

    const int y0 = n0 / I_TOK;
    const int b1 = (y0 + 1) * I_TOK - n0;
    const int ylast = (n0 + BN - 1) / I_TOK;

    bool vm_ok[4][2]; bool seg1[4][2];
#pragma unroll
    for (int nt = 0; nt < 4; nt++)
#pragma unroll
        for (int cc = 0; cc < 2; cc++) {
            int nl = wn * 32 + nt * 8 + 2 * tig + cc;
            vm_ok[nt][cc] = s_vm[nl] != 0;
            seg1[nt][cc] = nl >= b1;
        }
    int mrow[4][2]; bool tm_ok[4][2];
#pragma unroll
    for (int mt = 0; mt < 4; mt++)
#pragma unroll
        for (int gg = 0; gg < 2; gg++) {
            int ml = wm * 64 + mt * 16 + g + gg * 8;
            mrow[mt][gg] = ml;
            tm_ok[mt][gg] = s_tm[ml] != 0;
        }

    // rowmax: per (mt,gg) per seg, reduce across quad (cols), lane tig==0 atomics
#pragma unroll
    for (int mt = 0; mt < 4; mt++)
#pragma unroll
        for (int gg = 0; gg < 2; gg++) {
            float mx0 = -FLT_MAX, mx1 = -FLT_MAX;
#pragma unroll
            for (int nt = 0; nt < 4; nt++)
#pragma unroll
                for (int cc = 0; cc < 2; cc++) {
                    if (!vm_ok[nt][cc]) continue;
                    float v = acc[mt][nt][gg * 2 + cc];
                    if (seg1[nt][cc]) mx1 = fmaxf(mx1, v);
                    else              mx0 = fmaxf(mx0, v);
                }
#pragma unroll
            for (int o = 1; o <= 2; o <<= 1) {
                mx0 = fmaxf(mx0, __shfl_xor_sync(0xffffffffu, mx0, o));
                mx1 = fmaxf(mx1, __shfl_xor_sync(0xffffffffu, mx1, o));
            }
            if (tig == 0) {
                if (mx0 > -FLT_MAX) atomicMax(&s_row[mrow[mt][gg]][0], enc_f(mx0));
                if (mx1 > -FLT_MAX) atomicMax(&s_row[mrow[mt][gg]][1], enc_f(mx1));
            }
        }

    // colmax + fused i2t partial sums (each warp exclusively owns its columns
    // within its x-half; masked sums atomicAdd'ed into g_i2t_sum)
    {
        float sum0 = 0.f, sum1 = 0.f;
#pragma unroll
        for (int nt = 0; nt < 4; nt++)
#pragma unroll
            for (int cc = 0; cc < 2; cc++) {
                float mx = -FLT_MAX;
#pragma unroll
                for (int mt = 0; mt < 4; mt++)
#pragma unroll
                    for (int gg = 0; gg < 2; gg++)
                        if (tm_ok[mt][gg]) mx = fmaxf(mx, acc[mt][nt][gg * 2 + cc]);
#pragma unroll
                for (int o = 4; o <= 16; o <<= 1)
                    mx = fmaxf(mx, __shfl_xor_sync(0xffffffffu, mx, o));
                if (g == 0 && vm_ok[nt][cc]) {
                    if (seg1[nt][cc]) sum1 += mx;
                    else              sum0 += mx;
                }
            }
#pragma unroll
        for (int o = 1; o <= 2; o <<= 1) {
            sum0 += __shfl_xor_sync(0xffffffffu, sum0, o);
            sum1 += __shfl_xor_sync(0xffffffffu, sum1, o);
        }
        if (lane == 0) {
            const int x = (m0 >> 6) + wm;
            atomicAdd(&g_i2t_sum[x * B_SZ + y0], sum0);
            if (y0 + 1 <= ylast) atomicAdd(&g_i2t_sum[x * B_SZ + y0 + 1], sum1);
        }
    }
    __syncthreads();

    // flush rowmax to global
    for (int e = tid; e < BM * 2; e += 256) {
        const int rr = e >> 1, seg = e & 1;
        if (y0 + seg > ylast) continue;
        const unsigned v = s_row[rr][seg];
        if (v != ENC_NEG)
            atomicMax(&g_rowmax[(size_t)(m0 + rr) * B_SZ + y0 + seg], v);
    }
}

// ---------------- means + finalize (last-block trick, coalesced) ----------------
__global__ void means_kernel(const unsigned char* __restrict__ tmask,
                             const unsigned char* __restrict__ vmask,
                             float* __restrict__ out)
{
    __shared__ float sh_s1[4][B_SZ];
    __shared__ float sh_c1[4];
    __shared__ float sh_e1[B_SZ];
    __shared__ float sh_red[2][2];
    __shared__ int s_last;
    const int x = blockIdx.x;
    const int tid = threadIdx.x;          // 256
    const int tg = tid >> 6, y = tid & 63;   // coalesced: lanes sweep y
    const float temp = expf(logf((float)(1.0 / 0.07)));

    // t2i: coalesced partial sums over t in {tg, tg+4, ...}
    float s1 = 0.f, c1 = 0.f;
    for (int t = tg; t < B_SZ; t += 4) {
        if (tmask[x * B_SZ + t]) {
            s1 += dec_f(g_rowmax[(size_t)(x * B_SZ + t) * B_SZ + y]);
            c1 += 1.f;
        }
    }
    sh_s1[tg][y] = s1;
    if (y == 0) sh_c1[tg] = c1;

    // i2t counts: coalesced vmask scan, y-th group of I_TOK bytes per 4 threads
    // (use same tg/y layout: thread (tg,y) counts vmask[y*196 + i], i in tg-strided)
    float c2 = 0.f;
    for (int i = tg; i < I_TOK; i += 4)
        c2 += vmask[y * I_TOK + i] ? 1.f : 0.f;
    // reduce c2 across the 4 tg groups holding the same y via smem reuse
    __syncthreads();

    if (tg == 0) {
        const float S1 = sh_s1[0][y] + sh_s1[1][y] + sh_s1[2][y] + sh_s1[3][y];
        const float C1 = sh_c1[0] + sh_c1[1] + sh_c1[2] + sh_c1[3];
        // gather c2 partials for this y from the other 3 groups via shfl is not
        // possible (different warps) -> recompute: c2 totals via atomic-free trick:
        // store partials in sh_s1 (reused) after sync
        sh_s1[0][y] = 0.f;   // placeholder; replaced below
        const float t2i = temp * (S1 / fmaxf(C1, 1e-6f));
        sh_e1[y] = t2i;      // stash t2i temporarily (exp applied after c2 ready)
    }
    // write c2 partials (all groups) into sh_s1 rows for reduction
    __syncthreads();
    sh_s1[tg][y] = c2;
    __syncthreads();

    if (tg == 0) {
        const float C2 = sh_s1[0][y] + sh_s1[1][y] + sh_s1[2][y] + sh_s1[3][y];
        const float t2i = sh_e1[y];
        const float i2t = temp * (g_i2t_sum[x * B_SZ + y] / fmaxf(C2, 1e-6f));
        const float e1 = expf(t2i), e2 = expf(i2t);
        sh_e1[y] = e1;
        atomicAdd(&g_i2t_den[y], e2);
        if (y == x) { g_d1[x] = e1; g_d2[x] = e2; }
    }
    __syncthreads();
    if (tid == 0) {
        float acc = 0.f;
        for (int k = 0; k < B_SZ; k++) acc += sh_e1[k];
        g_t2i_den[x] = acc;
        __threadfence();
        s_last = (atomicAdd(&g_ctr, 1) == B_SZ - 1);
    }
    __syncthreads();
    if (!s_last) return;
    __threadfence();

    float l1 = 0.f, l2 = 0.f;
    if (tid < B_SZ) {
        l1 = -logf(g_d1[tid] + 1e-20f) + logf(g_t2i_den[tid] + 1e-20f);
        l2 = -logf(g_d2[tid] + 1e-20f) + logf(g_i2t_den[tid] + 1e-20f);
#pragma unroll
        for (int o = 16; o > 0; o >>= 1) {
            l1 += __shfl_xor_sync(0xffffffffu, l1, o);
            l2 += __shfl_xor_sync(0xffffffffu, l2, o);
        }
        if ((tid & 31) == 0) { sh_red[0][tid >> 5] = l1; sh_red[1][tid >> 5] = l2; }
    }
    __syncthreads();
    if (tid == 0) {
        float a = (sh_red[0][0] + sh_red[0][1]) * (1.f / 64.f);
        float b = (sh_red[1][0] + sh_red[1][1]) * (1.f / 64.f);
        out[0] = 0.5f * (a + b);
        out[1] = a;
        out[2] = b;
    }
}

extern "C" void kernel_launch(void* const* d_in, const int* in_sizes, int n_in,
                              void* d_out, int out_size)
{
    const float *vision, *text;
    const unsigned char *vmask, *tmask;
    if (in_sizes[0] == N_TOT * D_K) {
        vision = (const float*)d_in[0];
        text   = (const float*)d_in[1];
    } else {
        vision = (const float*)d_in[1];
        text   = (const float*)d_in[0];
    }
    if (in_sizes[2] == N_TOT) {
        vmask = (const unsigned char*)d_in[2];
        tmask = (const unsigned char*)d_in[3];
    } else {
        vmask = (const unsigned char*)d_in[3];
        tmask = (const unsigned char*)d_in[2];
    }
    float* out = (float*)d_out;

    cudaFuncSetAttribute(gemm_max_kernel,
                         cudaFuncAttributeMaxDynamicSharedMemorySize, DSMEM_BYTES);

    const int groups = (M_TOT + N_TOT) * D_K / 8;
    convert_kernel<<<(groups + 255) / 256, 256>>>(text, vision);
    gemm_max_kernel<<<NT_M * NT_N, 256, DSMEM_BYTES>>>(tmask, vmask);
    means_kernel<<<B_SZ, 256>>>(tmask, vmask, out);
}